// round 6
// baseline (speedup 1.0000x reference)
#include <cuda_runtime.h>
#include <cuda_bf16.h>
#include <math.h>
#include <stdint.h>
#include <mma.h>

using namespace nvcuda;

#define BATCH 16384

// ---------------- scratch (static device arrays; no allocations) ----------------
__device__ float g_h400 [BATCH*400];
__device__ float g_out  [BATCH*256];
__device__ float g_tmp  [BATCH*256];
__device__ float g_emb  [BATCH*256];
__device__ float g_si   [BATCH*256];
__device__ float g_logit[BATCH*64];
__device__ float g_gsel [3*BATCH*64];
__device__ float g_fraw [BATCH*8];
__device__ float g_fsel [BATCH*8];
__device__ float g_hbig [(size_t)BATCH*2048];   // [B][2048], col = m*256+n
__device__ float g_W2   [256*2048];             // [d][m*256+n] scaled mod weights

// deterministic two-stage batchnorm reductions (no atomics)
#define NPART 64
__device__ float g_psum1[NPART*256],  g_psq1[NPART*256];
__device__ float g_psum2[NPART*2048], g_psq2[NPART*2048];
__device__ float g_mean1[256],  g_istd1[256];
__device__ float g_mean2[2048], g_istd2[2048];

enum { EPI_NONE=0, EPI_RELU=1, EPI_TANH=2, EPI_MULRELU=3, EPI_DUAL=4 };

// =======================================================================
//  Split-BF16 tensor-core GEMM (proven R5 pattern, straight-line):
//  C = A@B (+bias, +epilogue). 128x128 tile, 256 thr, 8 warps x (64x32).
//  If bias==nullptr && epi==EPI_NONE: direct store_matrix_sync to C.
//  Else: per-warp staging through a SEPARATE smem region.
// =======================================================================
#define ASTRB 40    // A smem row stride (bf16): hi at k 0..15, lo at 16..31
#define BSTRB 264   // B smem row stride (bf16): hi at n 0..127, lo at 128..255
#define STG_LD 36   // f32 staging row stride

__global__ void __launch_bounds__(256) tgemm_tc(
    const float* __restrict__ A, const float* __restrict__ Bw,
    const float* __restrict__ bias, float* __restrict__ C,
    float* __restrict__ C2, int N, int K, int epi)
{
    __shared__ __align__(32) __nv_bfloat16 As[128*ASTRB];
    __shared__ __align__(32) __nv_bfloat16 Bs[16*BSTRB];
    __shared__ __align__(16) float Stg[8*16*STG_LD];

    const int tid  = threadIdx.x;
    const int lane = tid & 31, wid = tid >> 5;
    const int warpM = (wid >> 2) * 64, warpN = (wid & 3) * 32;
    const int rowBase = blockIdx.y * 128, colBase = blockIdx.x * 128;

    const int aRow = tid >> 1,  aK = (tid & 1) * 8;   // A: 128 rows x 16 k
    const int bK   = tid >> 4,  bN = (tid & 15) * 8;  // B: 16 k x 128 n

    wmma::fragment<wmma::accumulator,16,16,16,float> acc[4][2];
    #pragma unroll
    for (int mt=0;mt<4;mt++)
        #pragma unroll
        for (int nt=0;nt<2;nt++)
            wmma::fill_fragment(acc[mt][nt], 0.f);

    for (int kt = 0; kt < K; kt += 16) {
        // --- A tile, split hi/lo ---
        {
            const float* ap = A + (size_t)(rowBase + aRow) * K + kt + aK;
            #pragma unroll
            for (int e=0;e<8;e++) {
                float v = ap[e];
                __nv_bfloat16 h = __float2bfloat16(v);
                __nv_bfloat16 l = __float2bfloat16(v - __bfloat162float(h));
                As[aRow*ASTRB + aK + e]      = h;
                As[aRow*ASTRB + aK + e + 16] = l;
            }
        }
        // --- B tile, split hi/lo (N-edge guarded) ---
        {
            int gc = colBase + bN;
            const float* bp = Bw + (size_t)(kt + bK) * N + gc;
            #pragma unroll
            for (int e=0;e<8;e++) {
                float v = (gc + e < N) ? bp[e] : 0.f;
                __nv_bfloat16 h = __float2bfloat16(v);
                __nv_bfloat16 l = __float2bfloat16(v - __bfloat162float(h));
                Bs[bK*BSTRB + bN + e]       = h;
                Bs[bK*BSTRB + bN + e + 128] = l;
            }
        }
        __syncthreads();

        wmma::fragment<wmma::matrix_a,16,16,16,__nv_bfloat16,wmma::row_major> ah[4], al[4];
        wmma::fragment<wmma::matrix_b,16,16,16,__nv_bfloat16,wmma::row_major> bh[2], bl[2];
        #pragma unroll
        for (int mt=0;mt<4;mt++) {
            wmma::load_matrix_sync(ah[mt], &As[(warpM + mt*16)*ASTRB],      ASTRB);
            wmma::load_matrix_sync(al[mt], &As[(warpM + mt*16)*ASTRB + 16], ASTRB);
        }
        #pragma unroll
        for (int nt=0;nt<2;nt++) {
            wmma::load_matrix_sync(bh[nt], &Bs[warpN + nt*16],       BSTRB);
            wmma::load_matrix_sync(bl[nt], &Bs[warpN + nt*16 + 128], BSTRB);
        }
        #pragma unroll
        for (int mt=0;mt<4;mt++)
            #pragma unroll
            for (int nt=0;nt<2;nt++) {
                wmma::mma_sync(acc[mt][nt], ah[mt], bh[nt], acc[mt][nt]);
                wmma::mma_sync(acc[mt][nt], ah[mt], bl[nt], acc[mt][nt]);
                wmma::mma_sync(acc[mt][nt], al[mt], bh[nt], acc[mt][nt]);
            }
        __syncthreads();
    }

    if (bias == nullptr && epi == EPI_NONE) {
        // direct store (N must be multiple of 16, block fully in-range)
        #pragma unroll
        for (int mt=0; mt<4; mt++) {
            float* dst = C + (size_t)(rowBase + warpM + mt*16) * N + colBase + warpN;
            wmma::store_matrix_sync(dst,      acc[mt][0], N, wmma::mem_row_major);
            wmma::store_matrix_sync(dst + 16, acc[mt][1], N, wmma::mem_row_major);
        }
        return;
    }

    // staged epilogue: separate smem region, N multiple of 16 -> whole 16-strips
    float* stg = &Stg[wid * (16*STG_LD)];
    const int r  = lane >> 1;
    const int cb = (lane & 1) * 16;
    #pragma unroll
    for (int mt=0; mt<4; mt++) {
        wmma::store_matrix_sync(stg,      acc[mt][0], STG_LD, wmma::mem_row_major);
        wmma::store_matrix_sync(stg + 16, acc[mt][1], STG_LD, wmma::mem_row_major);
        __syncwarp();
        int row  = rowBase + warpM + mt*16 + r;
        int col0 = colBase + warpN + cb;
        if (col0 < N) {
            size_t base = (size_t)row * N + col0;
            #pragma unroll
            for (int e=0;e<16;e++) {
                float v = stg[r*STG_LD + cb + e] + bias[col0 + e];
                if      (epi == EPI_NONE) C[base + e] = v;
                else if (epi == EPI_RELU) C[base + e] = fmaxf(v, 0.f);
                else { C[base + e] = v; C2[base + e] = fmaxf(v, 0.f); }  // DUAL
            }
        }
        __syncwarp();
    }
}

// ---------------- scaled mod weights: W2[d][m*256+n] = istd1[d]*g1[m,d]*W[m,d,n] ----------------
__global__ void scaleW(const float* __restrict__ modW, const float* __restrict__ g1)
{
    int idx = blockIdx.x*256 + threadIdx.x;     // 524288 total
    int d = idx >> 11;
    int c = idx & 2047;
    int m = c >> 8;
    int n = c & 255;
    g_W2[idx] = g_istd1[d] * g1[m*256 + d] * modW[((size_t)(m*256 + d))*256 + n];
}

// ---------------- generic fp32 SGEMM (small precision-sensitive GEMMs) ----------------
__global__ void __launch_bounds__(256) sgemm(
    const float* __restrict__ A, const float* __restrict__ Bw,
    const float* __restrict__ bias, float* __restrict__ C,
    float* __restrict__ C2, const float* __restrict__ aux,
    int N, int K, int epi)
{
    __shared__ float As[16][128];
    __shared__ float Bs[16][128];
    int tid = threadIdx.x;
    int tx = tid & 15, ty = tid >> 4;
    int rowBase = blockIdx.y * 128;
    int colBase = blockIdx.x * 128;

    float acc[8][8];
    #pragma unroll
    for (int i=0;i<8;i++)
        #pragma unroll
        for (int j=0;j<8;j++) acc[i][j]=0.f;

    int aRow = tid >> 1;
    int aCol = (tid & 1) * 8;
    int bRow = tid >> 4;
    int bCol = (tid & 15) * 8;

    for (int kt = 0; kt < K; kt += 16) {
        {
            const float* ap = A + (size_t)(rowBase + aRow) * K + kt + aCol;
            float4 v0 = *(const float4*)(ap);
            float4 v1 = *(const float4*)(ap + 4);
            As[aCol+0][aRow]=v0.x; As[aCol+1][aRow]=v0.y; As[aCol+2][aRow]=v0.z; As[aCol+3][aRow]=v0.w;
            As[aCol+4][aRow]=v1.x; As[aCol+5][aRow]=v1.y; As[aCol+6][aRow]=v1.z; As[aCol+7][aRow]=v1.w;
        }
        {
            int gc = colBase + bCol;
            const float* bp = Bw + (size_t)(kt + bRow) * N + gc;
            if (gc + 7 < N) {
                *(float4*)&Bs[bRow][bCol]   = *(const float4*)(bp);
                *(float4*)&Bs[bRow][bCol+4] = *(const float4*)(bp + 4);
            } else {
                #pragma unroll
                for (int e=0;e<8;e++)
                    Bs[bRow][bCol+e] = (gc+e < N) ? bp[e] : 0.f;
            }
        }
        __syncthreads();
        #pragma unroll
        for (int k=0;k<16;k++) {
            float4 a0 = *(const float4*)&As[k][ty*8];
            float4 a1 = *(const float4*)&As[k][ty*8+4];
            float4 b0 = *(const float4*)&Bs[k][tx*8];
            float4 b1 = *(const float4*)&Bs[k][tx*8+4];
            float av[8]={a0.x,a0.y,a0.z,a0.w,a1.x,a1.y,a1.z,a1.w};
            float bv[8]={b0.x,b0.y,b0.z,b0.w,b1.x,b1.y,b1.z,b1.w};
            #pragma unroll
            for (int i=0;i<8;i++)
                #pragma unroll
                for (int j=0;j<8;j++)
                    acc[i][j] += av[i]*bv[j];
        }
        __syncthreads();
    }

    #pragma unroll
    for (int i=0;i<8;i++) {
        int row = rowBase + ty*8 + i;
        #pragma unroll
        for (int j=0;j<8;j++) {
            int col = colBase + tx*8 + j;
            if (col < N) {
                float v = acc[i][j] + bias[col];
                size_t idx = (size_t)row * N + col;
                if      (epi == EPI_NONE)    C[idx] = v;
                else if (epi == EPI_RELU)    C[idx] = fmaxf(v, 0.f);
                else if (epi == EPI_TANH)    C[idx] = tanhf(v);
                else if (epi == EPI_MULRELU) C[idx] = fmaxf(v * aux[idx], 0.f);
                else                         { C[idx] = v; C2[idx] = fmaxf(v, 0.f); }
            }
        }
    }
}

// ---------------- batchnorm stats (deterministic 2-stage, generic ncols) ----------------
__global__ void colstats(const float* __restrict__ X,
                         float* __restrict__ psum, float* __restrict__ psq,
                         int ncols)
{
    int c = blockIdx.x*256 + threadIdx.x;
    int rpb = BATCH / NPART;
    int r0  = blockIdx.y * rpb;
    float s = 0.f, q = 0.f;
    for (int r = r0; r < r0 + rpb; r++) {
        float v = X[(size_t)r*ncols + c];
        s += v; q += v*v;
    }
    psum[(size_t)blockIdx.y*ncols + c] = s;
    psq [(size_t)blockIdx.y*ncols + c] = q;
}

__global__ void bnfinal(const float* __restrict__ psum, const float* __restrict__ psq,
                        float* __restrict__ mean, float* __restrict__ istd, int n)
{
    int i = blockIdx.x*blockDim.x + threadIdx.x;
    if (i >= n) return;
    float s = 0.f, q = 0.f;
    for (int p = 0; p < NPART; p++) { s += psum[(size_t)p*n + i]; q += psq[(size_t)p*n + i]; }
    float mu  = s * (1.f/BATCH);
    float var = q * (1.f/BATCH) - mu*mu;
    mean[i] = mu;
    istd[i] = rsqrtf(var + 1e-5f);
}

// ---------------- gumbel softmax ----------------
__device__ __forceinline__ float gnoise(float u) {
    u = fminf(fmaxf(u, 1e-10f), 1.0f - 1e-7f);
    return -logf(-logf(u));
}

__global__ void gumbel_sel(const float* __restrict__ u, int i)
{
    int t = blockIdx.x*blockDim.x + threadIdx.x;
    if (t >= BATCH*8) return;
    int b = t >> 3, m = t & 7;
    const float* lp = g_logit + b*64 + m*8;
    const float* up = u + (size_t)b*192 + i*64 + m*8;
    float z[8]; float mx = -3.4e38f;
    #pragma unroll
    for (int k=0;k<8;k++){ z[k] = lp[k] + gnoise(up[k]); mx = fmaxf(mx, z[k]); }
    float s = 0.f;
    #pragma unroll
    for (int k=0;k<8;k++){ z[k] = expf(z[k]-mx); s += z[k]; }
    float inv = 1.f/s;
    float* op = g_gsel + (size_t)i*BATCH*64 + b*64 + m*8;
    #pragma unroll
    for (int k=0;k<8;k++) op[k] = z[k]*inv;
}

__global__ void gumbel_fin(const float* __restrict__ u)
{
    int b = blockIdx.x*blockDim.x + threadIdx.x;
    if (b >= BATCH) return;
    float z[8]; float mx = -3.4e38f;
    #pragma unroll
    for (int k=0;k<8;k++){ z[k] = g_fraw[b*8+k] + gnoise(u[b*8+k]); mx = fmaxf(mx, z[k]); }
    float s = 0.f;
    #pragma unroll
    for (int k=0;k<8;k++){ z[k] = expf(z[k]-mx); s += z[k]; }
    float inv = 1.f/s;
    #pragma unroll
    for (int k=0;k<8;k++) g_fsel[b*8+k] = z[k]*inv;
}

// ---------------- final select logits ----------------
__global__ void __launch_bounds__(256) gemm_selF(const float* __restrict__ W, const float* __restrict__ bias)
{
    __shared__ float Ws[2048];
    int tid = threadIdx.x;
    for (int idx = tid; idx < 2048; idx += 256) Ws[idx] = W[idx];
    __syncthreads();
    int b = blockIdx.x*32 + (tid >> 3);
    int n = tid & 7;
    const float* ap = g_si + (size_t)b*256;
    float acc = bias[n];
    #pragma unroll 8
    for (int k=0;k<256;k++) acc += ap[k]*Ws[k*8+n];
    g_fraw[b*8+n] = acc;
}

// ---------------- fused bn2 + select cascade + final select + last GEMM ----------------
__global__ void __launch_bounds__(256) cascade(
    const float* __restrict__ g2, const float* __restrict__ b2,
    const float* __restrict__ lastW, const float* __restrict__ lastb,
    float* __restrict__ out)
{
    int b = blockIdx.x;
    int tid = threadIdx.x;
    __shared__ float Ssh[64];
    __shared__ float fs[8];
    __shared__ float ov[256];

    float p[8];
    #pragma unroll
    for (int m=0;m<8;m++) {
        int c = m*256 + tid;
        float v = g_hbig[(size_t)b*2048 + c];
        p[m] = (v - g_mean2[c]) * g_istd2[c] * g2[c] + b2[c];
    }

    for (int l=0;l<3;l++) {
        if (tid < 64) Ssh[tid] = g_gsel[(size_t)(2-l)*BATCH*64 + (size_t)b*64 + tid];
        __syncthreads();
        float np[8];
        #pragma unroll
        for (int m=0;m<8;m++) {
            float a = 0.f;
            #pragma unroll
            for (int k=0;k<8;k++) a += Ssh[m*8+k]*p[k];
            np[m] = fmaxf(a, 0.f);
        }
        #pragma unroll
        for (int m=0;m<8;m++) p[m] = np[m];
        __syncthreads();
    }

    if (tid < 8) fs[tid] = g_fsel[b*8+tid];
    __syncthreads();
    float o = 0.f;
    #pragma unroll
    for (int m=0;m<8;m++) o += fs[m]*p[m];
    ov[tid] = o;
    __syncthreads();

    if (tid < 18) {
        float acc = lastb[tid];
        for (int k=0;k<256;k++) acc += ov[k]*lastW[k*18+tid];
        out[(size_t)b*18 + tid] = acc;
    }
}

// ---------------- launch ----------------
extern "C" void kernel_launch(void* const* d_in, const int* in_sizes, int n_in,
                              void* d_out, int out_size)
{
    const float* x       = (const float*)d_in[0];
    const float* embIn   = (const float*)d_in[1];
    const float* u_sel   = (const float*)d_in[2];
    const float* u_fin   = (const float*)d_in[3];
    const float* base_W0 = (const float*)d_in[4];
    const float* base_b0 = (const float*)d_in[5];
    const float* base_W1 = (const float*)d_in[6];
    const float* base_b1 = (const float*)d_in[7];
    const float* em_W0   = (const float*)d_in[8];
    const float* em_b0   = (const float*)d_in[9];
    const float* gat_W0  = (const float*)d_in[10];
    const float* gat_b0  = (const float*)d_in[11];
    const float* gat_W1  = (const float*)d_in[12];
    const float* gat_b1  = (const float*)d_in[13];
    const float* sel_W   = (const float*)d_in[14];
    const float* sel_b   = (const float*)d_in[15];
    const float* selF_W  = (const float*)d_in[16];
    const float* selF_b  = (const float*)d_in[17];
    const float* cond_W  = (const float*)d_in[18];
    const float* cond_b  = (const float*)d_in[19];
    const float* mod_W   = (const float*)d_in[20];
    const float* mod_b   = (const float*)d_in[21];   // cancelled by bn2 (unused)
    const float* last_W  = (const float*)d_in[22];
    const float* last_b  = (const float*)d_in[23];
    const float* bn1_g   = (const float*)d_in[24];
    const float* bn1_b   = (const float*)d_in[25];   // cancelled by bn2 (unused)
    const float* bn2_g   = (const float*)d_in[26];
    const float* bn2_b   = (const float*)d_in[27];
    float* out = (float*)d_out;
    (void)mod_b; (void)bn1_b;

    float *p_h400, *p_out, *p_tmp, *p_emb, *p_si, *p_logit, *p_hbig, *p_W2;
    float *p_psum1, *p_psq1, *p_psum2, *p_psq2, *p_mean1, *p_istd1, *p_mean2, *p_istd2;
    cudaGetSymbolAddress((void**)&p_h400,  g_h400);
    cudaGetSymbolAddress((void**)&p_out,   g_out);
    cudaGetSymbolAddress((void**)&p_tmp,   g_tmp);
    cudaGetSymbolAddress((void**)&p_emb,   g_emb);
    cudaGetSymbolAddress((void**)&p_si,    g_si);
    cudaGetSymbolAddress((void**)&p_logit, g_logit);
    cudaGetSymbolAddress((void**)&p_hbig,  g_hbig);
    cudaGetSymbolAddress((void**)&p_W2,    g_W2);
    cudaGetSymbolAddress((void**)&p_psum1, g_psum1);
    cudaGetSymbolAddress((void**)&p_psq1,  g_psq1);
    cudaGetSymbolAddress((void**)&p_psum2, g_psum2);
    cudaGetSymbolAddress((void**)&p_psq2,  g_psq2);
    cudaGetSymbolAddress((void**)&p_mean1, g_mean1);
    cudaGetSymbolAddress((void**)&p_istd1, g_istd1);
    cudaGetSymbolAddress((void**)&p_mean2, g_mean2);
    cudaGetSymbolAddress((void**)&p_istd2, g_istd2);

    dim3 blk(256);
    auto grid2 = [](int N){ return dim3((unsigned)((N+127)/128), BATCH/128); };

    // base path (TC): out = relu(x@W0+b0)@W1 + b1
    tgemm_tc<<<grid2(400), blk>>>(x,      base_W0, base_b0, p_h400, nullptr, 400, 128, EPI_RELU);
    tgemm_tc<<<grid2(256), blk>>>(p_h400, base_W1, base_b1, p_out,  nullptr, 256, 400, EPI_NONE);

    // embedding path (TC)
    tgemm_tc<<<grid2(400), blk>>>(embIn,  em_W0,  em_b0,  p_h400, nullptr, 400, 128, EPI_RELU);
    tgemm_tc<<<grid2(256), blk>>>(p_h400, gat_W0, gat_b0, p_tmp,  nullptr, 256, 400, EPI_RELU);
    tgemm_tc<<<grid2(256), blk>>>(p_tmp,  gat_W1, gat_b1, p_emb,  p_si,    256, 256, EPI_DUAL);

    // select loop (fp32 for precision)
    for (int i = 0; i < 3; i++) {
        sgemm<<<grid2(64),  blk>>>(p_si, sel_W + (size_t)i*256*64, sel_b + i*64,
                                   p_logit, nullptr, nullptr, 64, 256, EPI_TANH);
        gumbel_sel<<<(BATCH*8+255)/256, blk>>>(u_sel, i);
        sgemm<<<grid2(256), blk>>>(p_logit, cond_W + (size_t)i*64*256, cond_b + i*256,
                                   p_si, nullptr, p_emb, 256, 64, EPI_MULRELU);
    }

    // final select
    gemm_selF<<<BATCH/32, blk>>>(selF_W, selF_b);
    gumbel_fin<<<(BATCH+255)/256, blk>>>(u_fin);

    // bn1 stats over g_out
    colstats<<<dim3(1, NPART), blk>>>(p_out, p_psum1, p_psq1, 256);
    bnfinal<<<1, blk>>>(p_psum1, p_psq1, p_mean1, p_istd1, 256);

    // fold istd1*bn1_g into mod weights (all per-column shifts cancel in bn2)
    scaleW<<<2048, blk>>>(mod_W, bn1_g);

    // mod einsum as ONE plain TC GEMM: hbig[B][2048] = g_out @ W2
    tgemm_tc<<<grid2(2048), blk>>>(p_out, p_W2, nullptr, p_hbig, nullptr, 2048, 256, EPI_NONE);

    // bn2 stats over hbig [B][2048]
    colstats<<<dim3(8, NPART), blk>>>(p_hbig, p_psum2, p_psq2, 2048);
    bnfinal<<<8, blk>>>(p_psum2, p_psq2, p_mean2, p_istd2, 2048);

    // fused bn2 + cascade + final select + last layer
    cascade<<<BATCH, blk>>>(bn2_g, bn2_b, last_W, last_b, out);
}

// round 7
// speedup vs baseline: 1.3232x; 1.3232x over previous
#include <cuda_runtime.h>
#include <cuda_bf16.h>
#include <math.h>
#include <stdint.h>
#include <mma.h>

using namespace nvcuda;

#define BATCH 16384

// ---------------- scratch (static device arrays; no allocations) ----------------
__device__ float g_h400 [BATCH*400];
__device__ float g_out  [BATCH*256];
__device__ float g_tmp  [BATCH*256];
__device__ float g_emb  [BATCH*256];
__device__ float g_si   [BATCH*256];
__device__ float g_logit[BATCH*64];
__device__ float g_gsel [3*BATCH*64];
__device__ float g_fraw [BATCH*8];
__device__ float g_fsel [BATCH*8];
__device__ float g_hbig [(size_t)BATCH*2048];   // [B][2048], col = m*256+n
__device__ float g_W2   [256*2048];             // [d][m*256+n] scaled mod weights

// deterministic two-stage batchnorm reductions (no atomics)
#define NPART 64
__device__ float g_psum1[NPART*256],  g_psq1[NPART*256];
__device__ float g_psum2[NPART*2048], g_psq2[NPART*2048];
__device__ float g_mean1[256],  g_istd1[256];
__device__ float g_mean2[2048], g_istd2[2048];

enum { EPI_NONE=0, EPI_RELU=1, EPI_TANH=2, EPI_MULRELU=3, EPI_DUAL=4 };

// =======================================================================
//  Split-BF16 TC GEMM v2: BK=32, vectorized loads, packed uint4 smem
//  stores, staged epilogue (tanh/mulrelu/dual/relu) or direct store.
//  128x128x32 tile, 256 thr, 8 warps x (64x32).
// =======================================================================
#define ASTR2 72    // A smem row stride in bf16 (144B): 32 hi | 32 lo | pad
#define BSTR2 264   // B smem row stride in bf16 (528B): 128 hi | 128 lo | pad
#define STG_LD 36

__device__ __forceinline__ uint32_t pack_hi(float v0, float v1, float& r0, float& r1) {
    __nv_bfloat16 h0 = __float2bfloat16(v0);
    __nv_bfloat16 h1 = __float2bfloat16(v1);
    r0 = v0 - __bfloat162float(h0);
    r1 = v1 - __bfloat162float(h1);
    return (uint32_t)__bfloat16_as_ushort(h0) | ((uint32_t)__bfloat16_as_ushort(h1) << 16);
}
__device__ __forceinline__ uint32_t pack_lo(float r0, float r1) {
    __nv_bfloat16 l0 = __float2bfloat16(r0);
    __nv_bfloat16 l1 = __float2bfloat16(r1);
    return (uint32_t)__bfloat16_as_ushort(l0) | ((uint32_t)__bfloat16_as_ushort(l1) << 16);
}

__global__ void __launch_bounds__(256,2) tgemm_tc(
    const float* __restrict__ A, const float* __restrict__ Bw,
    const float* __restrict__ bias, float* __restrict__ C,
    float* __restrict__ C2, const float* __restrict__ aux,
    int N, int K, int epi)
{
    __shared__ __align__(16) char sh[128*ASTR2*2 + 32*BSTR2*2];  // 18432 + 16896 = 35328
    __nv_bfloat16* As = (__nv_bfloat16*)sh;
    __nv_bfloat16* Bs = (__nv_bfloat16*)(sh + 128*ASTR2*2);

    const int tid  = threadIdx.x;
    const int lane = tid & 31, wid = tid >> 5;
    const int warpM = (wid >> 2) * 64, warpN = (wid & 3) * 32;
    const int rowBase = blockIdx.y * 128, colBase = blockIdx.x * 128;

    const int aRow = tid >> 1, aKo = (tid & 1) * 16;   // A: 128 rows x 32 k
    const int bKr  = tid >> 3, bNo = (tid & 7) * 16;   // B: 32 k x 128 n

    wmma::fragment<wmma::accumulator,16,16,16,float> acc[4][2];
    #pragma unroll
    for (int mt=0;mt<4;mt++)
        #pragma unroll
        for (int nt=0;nt<2;nt++)
            wmma::fill_fragment(acc[mt][nt], 0.f);

    for (int kt = 0; kt < K; kt += 32) {
        // ---- A tile: 16 consecutive k per thread ----
        {
            float va[16];
            const float* ap = A + (size_t)(rowBase + aRow) * K + kt + aKo;
            if (kt + aKo + 15 < K) {
                float4 v0 = *(const float4*)(ap);
                float4 v1 = *(const float4*)(ap + 4);
                float4 v2 = *(const float4*)(ap + 8);
                float4 v3 = *(const float4*)(ap + 12);
                va[0]=v0.x; va[1]=v0.y; va[2]=v0.z; va[3]=v0.w;
                va[4]=v1.x; va[5]=v1.y; va[6]=v1.z; va[7]=v1.w;
                va[8]=v2.x; va[9]=v2.y; va[10]=v2.z; va[11]=v2.w;
                va[12]=v3.x; va[13]=v3.y; va[14]=v3.z; va[15]=v3.w;
            } else {
                #pragma unroll
                for (int e=0;e<16;e++) va[e] = (kt + aKo + e < K) ? ap[e] : 0.f;
            }
            uint32_t ph[8], pl[8];
            float r0, r1;
            #pragma unroll
            for (int e=0;e<8;e++) {
                ph[e] = pack_hi(va[2*e], va[2*e+1], r0, r1);
                pl[e] = pack_lo(r0, r1);
            }
            uint4* dh = (uint4*)((char*)As + aRow*144 + aKo*2);
            dh[0] = make_uint4(ph[0],ph[1],ph[2],ph[3]);
            dh[1] = make_uint4(ph[4],ph[5],ph[6],ph[7]);
            uint4* dl = (uint4*)((char*)As + aRow*144 + 64 + aKo*2);
            dl[0] = make_uint4(pl[0],pl[1],pl[2],pl[3]);
            dl[1] = make_uint4(pl[4],pl[5],pl[6],pl[7]);
        }
        // ---- B tile: 16 consecutive n per thread ----
        {
            float vb[16];
            int gc = colBase + bNo;
            const float* bp = Bw + (size_t)(kt + bKr) * N + gc;
            if (kt + bKr < K && gc + 15 < N) {
                float4 v0 = *(const float4*)(bp);
                float4 v1 = *(const float4*)(bp + 4);
                float4 v2 = *(const float4*)(bp + 8);
                float4 v3 = *(const float4*)(bp + 12);
                vb[0]=v0.x; vb[1]=v0.y; vb[2]=v0.z; vb[3]=v0.w;
                vb[4]=v1.x; vb[5]=v1.y; vb[6]=v1.z; vb[7]=v1.w;
                vb[8]=v2.x; vb[9]=v2.y; vb[10]=v2.z; vb[11]=v2.w;
                vb[12]=v3.x; vb[13]=v3.y; vb[14]=v3.z; vb[15]=v3.w;
            } else {
                bool krow_ok = (kt + bKr < K);
                #pragma unroll
                for (int e=0;e<16;e++) vb[e] = (krow_ok && gc + e < N) ? bp[e] : 0.f;
            }
            uint32_t ph[8], pl[8];
            float r0, r1;
            #pragma unroll
            for (int e=0;e<8;e++) {
                ph[e] = pack_hi(vb[2*e], vb[2*e+1], r0, r1);
                pl[e] = pack_lo(r0, r1);
            }
            uint4* dh = (uint4*)((char*)Bs + bKr*528 + bNo*2);
            dh[0] = make_uint4(ph[0],ph[1],ph[2],ph[3]);
            dh[1] = make_uint4(ph[4],ph[5],ph[6],ph[7]);
            uint4* dl = (uint4*)((char*)Bs + bKr*528 + 256 + bNo*2);
            dl[0] = make_uint4(pl[0],pl[1],pl[2],pl[3]);
            dl[1] = make_uint4(pl[4],pl[5],pl[6],pl[7]);
        }
        __syncthreads();

        #pragma unroll
        for (int ks=0; ks<32; ks+=16) {
            wmma::fragment<wmma::matrix_b,16,16,16,__nv_bfloat16,wmma::row_major> bh[2], bl[2];
            #pragma unroll
            for (int nt=0;nt<2;nt++) {
                wmma::load_matrix_sync(bh[nt], &Bs[ks*BSTR2 + warpN + nt*16],       BSTR2);
                wmma::load_matrix_sync(bl[nt], &Bs[ks*BSTR2 + 128 + warpN + nt*16], BSTR2);
            }
            #pragma unroll
            for (int mt=0;mt<4;mt++) {
                wmma::fragment<wmma::matrix_a,16,16,16,__nv_bfloat16,wmma::row_major> ah, al;
                wmma::load_matrix_sync(ah, &As[(warpM + mt*16)*ASTR2 + ks],      ASTR2);
                wmma::load_matrix_sync(al, &As[(warpM + mt*16)*ASTR2 + 32 + ks], ASTR2);
                #pragma unroll
                for (int nt=0;nt<2;nt++) {
                    wmma::mma_sync(acc[mt][nt], ah, bh[nt], acc[mt][nt]);
                    wmma::mma_sync(acc[mt][nt], ah, bl[nt], acc[mt][nt]);
                    wmma::mma_sync(acc[mt][nt], al, bh[nt], acc[mt][nt]);
                }
            }
        }
        __syncthreads();
    }

    if (bias == nullptr && epi == EPI_NONE) {
        // direct store (N multiple of 128 here)
        #pragma unroll
        for (int mt=0; mt<4; mt++) {
            float* dst = C + (size_t)(rowBase + warpM + mt*16) * N + colBase + warpN;
            wmma::store_matrix_sync(dst,      acc[mt][0], N, wmma::mem_row_major);
            wmma::store_matrix_sync(dst + 16, acc[mt][1], N, wmma::mem_row_major);
        }
        return;
    }

    // staged epilogue: staging overlays the A-tile region (all tile reads are
    // complete after the loop's trailing __syncthreads; per-warp regions disjoint)
    float* stg = (float*)sh + wid * (16*STG_LD);
    const int r  = lane >> 1;
    const int cb = (lane & 1) * 16;
    #pragma unroll
    for (int mt=0; mt<4; mt++) {
        wmma::store_matrix_sync(stg,      acc[mt][0], STG_LD, wmma::mem_row_major);
        wmma::store_matrix_sync(stg + 16, acc[mt][1], STG_LD, wmma::mem_row_major);
        __syncwarp();
        int row  = rowBase + warpM + mt*16 + r;
        int col0 = colBase + warpN + cb;
        if (col0 < N) {  // N multiple of 16 -> whole strips
            size_t base = (size_t)row * N + col0;
            #pragma unroll
            for (int e=0;e<16;e++) {
                float v = stg[r*STG_LD + cb + e] + bias[col0 + e];
                if      (epi == EPI_NONE)    C[base + e] = v;
                else if (epi == EPI_RELU)    C[base + e] = fmaxf(v, 0.f);
                else if (epi == EPI_TANH)    C[base + e] = tanhf(v);
                else if (epi == EPI_MULRELU) C[base + e] = fmaxf(v * aux[base + e], 0.f);
                else { C[base + e] = v; C2[base + e] = fmaxf(v, 0.f); }  // DUAL
            }
        }
        __syncwarp();
    }
}

// ---------------- scaled mod weights: W2[d][m*256+n] = istd1[d]*g1[m,d]*W[m,d,n] ----------------
__global__ void scaleW(const float* __restrict__ modW, const float* __restrict__ g1)
{
    int idx = blockIdx.x*256 + threadIdx.x;
    int d = idx >> 11;
    int c = idx & 2047;
    int m = c >> 8;
    int n = c & 255;
    g_W2[idx] = g_istd1[d] * g1[m*256 + d] * modW[((size_t)(m*256 + d))*256 + n];
}

// ---------------- batchnorm stats (deterministic 2-stage, generic ncols) ----------------
__global__ void colstats(const float* __restrict__ X,
                         float* __restrict__ psum, float* __restrict__ psq,
                         int ncols)
{
    int c = blockIdx.x*256 + threadIdx.x;
    int rpb = BATCH / NPART;
    int r0  = blockIdx.y * rpb;
    float s = 0.f, q = 0.f;
    for (int r = r0; r < r0 + rpb; r++) {
        float v = X[(size_t)r*ncols + c];
        s += v; q += v*v;
    }
    psum[(size_t)blockIdx.y*ncols + c] = s;
    psq [(size_t)blockIdx.y*ncols + c] = q;
}

__global__ void bnfinal(const float* __restrict__ psum, const float* __restrict__ psq,
                        float* __restrict__ mean, float* __restrict__ istd, int n)
{
    int i = blockIdx.x*blockDim.x + threadIdx.x;
    if (i >= n) return;
    float s = 0.f, q = 0.f;
    for (int p = 0; p < NPART; p++) { s += psum[(size_t)p*n + i]; q += psq[(size_t)p*n + i]; }
    float mu  = s * (1.f/BATCH);
    float var = q * (1.f/BATCH) - mu*mu;
    mean[i] = mu;
    istd[i] = rsqrtf(var + 1e-5f);
}

// ---------------- gumbel softmax ----------------
__device__ __forceinline__ float gnoise(float u) {
    u = fminf(fmaxf(u, 1e-10f), 1.0f - 1e-7f);
    return -logf(-logf(u));
}

__global__ void gumbel_sel(const float* __restrict__ u, int i)
{
    int t = blockIdx.x*blockDim.x + threadIdx.x;
    if (t >= BATCH*8) return;
    int b = t >> 3, m = t & 7;
    const float* lp = g_logit + b*64 + m*8;
    const float* up = u + (size_t)b*192 + i*64 + m*8;
    float z[8]; float mx = -3.4e38f;
    #pragma unroll
    for (int k=0;k<8;k++){ z[k] = lp[k] + gnoise(up[k]); mx = fmaxf(mx, z[k]); }
    float s = 0.f;
    #pragma unroll
    for (int k=0;k<8;k++){ z[k] = expf(z[k]-mx); s += z[k]; }
    float inv = 1.f/s;
    float* op = g_gsel + (size_t)i*BATCH*64 + b*64 + m*8;
    #pragma unroll
    for (int k=0;k<8;k++) op[k] = z[k]*inv;
}

__global__ void gumbel_fin(const float* __restrict__ u)
{
    int b = blockIdx.x*blockDim.x + threadIdx.x;
    if (b >= BATCH) return;
    float z[8]; float mx = -3.4e38f;
    #pragma unroll
    for (int k=0;k<8;k++){ z[k] = g_fraw[b*8+k] + gnoise(u[b*8+k]); mx = fmaxf(mx, z[k]); }
    float s = 0.f;
    #pragma unroll
    for (int k=0;k<8;k++){ z[k] = expf(z[k]-mx); s += z[k]; }
    float inv = 1.f/s;
    #pragma unroll
    for (int k=0;k<8;k++) g_fsel[b*8+k] = z[k]*inv;
}

// ---------------- final select logits ----------------
__global__ void __launch_bounds__(256) gemm_selF(const float* __restrict__ W, const float* __restrict__ bias)
{
    __shared__ float Ws[2048];
    int tid = threadIdx.x;
    for (int idx = tid; idx < 2048; idx += 256) Ws[idx] = W[idx];
    __syncthreads();
    int b = blockIdx.x*32 + (tid >> 3);
    int n = tid & 7;
    const float* ap = g_si + (size_t)b*256;
    float acc = bias[n];
    #pragma unroll 8
    for (int k=0;k<256;k++) acc += ap[k]*Ws[k*8+n];
    g_fraw[b*8+n] = acc;
}

// ---------------- fused bn2 + select cascade + final select + last GEMM ----------------
__global__ void __launch_bounds__(256) cascade(
    const float* __restrict__ g2, const float* __restrict__ b2,
    const float* __restrict__ lastW, const float* __restrict__ lastb,
    float* __restrict__ out)
{
    int b = blockIdx.x;
    int tid = threadIdx.x;
    __shared__ float Ssh[64];
    __shared__ float fs[8];
    __shared__ float ov[256];

    float p[8];
    #pragma unroll
    for (int m=0;m<8;m++) {
        int c = m*256 + tid;
        float v = g_hbig[(size_t)b*2048 + c];
        p[m] = (v - g_mean2[c]) * g_istd2[c] * g2[c] + b2[c];
    }

    for (int l=0;l<3;l++) {
        if (tid < 64) Ssh[tid] = g_gsel[(size_t)(2-l)*BATCH*64 + (size_t)b*64 + tid];
        __syncthreads();
        float np[8];
        #pragma unroll
        for (int m=0;m<8;m++) {
            float a = 0.f;
            #pragma unroll
            for (int k=0;k<8;k++) a += Ssh[m*8+k]*p[k];
            np[m] = fmaxf(a, 0.f);
        }
        #pragma unroll
        for (int m=0;m<8;m++) p[m] = np[m];
        __syncthreads();
    }

    if (tid < 8) fs[tid] = g_fsel[b*8+tid];
    __syncthreads();
    float o = 0.f;
    #pragma unroll
    for (int m=0;m<8;m++) o += fs[m]*p[m];
    ov[tid] = o;
    __syncthreads();

    if (tid < 18) {
        float acc = lastb[tid];
        for (int k=0;k<256;k++) acc += ov[k]*lastW[k*18+tid];
        out[(size_t)b*18 + tid] = acc;
    }
}

// ---------------- launch ----------------
extern "C" void kernel_launch(void* const* d_in, const int* in_sizes, int n_in,
                              void* d_out, int out_size)
{
    const float* x       = (const float*)d_in[0];
    const float* embIn   = (const float*)d_in[1];
    const float* u_sel   = (const float*)d_in[2];
    const float* u_fin   = (const float*)d_in[3];
    const float* base_W0 = (const float*)d_in[4];
    const float* base_b0 = (const float*)d_in[5];
    const float* base_W1 = (const float*)d_in[6];
    const float* base_b1 = (const float*)d_in[7];
    const float* em_W0   = (const float*)d_in[8];
    const float* em_b0   = (const float*)d_in[9];
    const float* gat_W0  = (const float*)d_in[10];
    const float* gat_b0  = (const float*)d_in[11];
    const float* gat_W1  = (const float*)d_in[12];
    const float* gat_b1  = (const float*)d_in[13];
    const float* sel_W   = (const float*)d_in[14];
    const float* sel_b   = (const float*)d_in[15];
    const float* selF_W  = (const float*)d_in[16];
    const float* selF_b  = (const float*)d_in[17];
    const float* cond_W  = (const float*)d_in[18];
    const float* cond_b  = (const float*)d_in[19];
    const float* mod_W   = (const float*)d_in[20];
    const float* mod_b   = (const float*)d_in[21];   // cancelled by bn2 (unused)
    const float* last_W  = (const float*)d_in[22];
    const float* last_b  = (const float*)d_in[23];
    const float* bn1_g   = (const float*)d_in[24];
    const float* bn1_b   = (const float*)d_in[25];   // cancelled by bn2 (unused)
    const float* bn2_g   = (const float*)d_in[26];
    const float* bn2_b   = (const float*)d_in[27];
    float* out = (float*)d_out;
    (void)mod_b; (void)bn1_b;

    float *p_h400, *p_out, *p_tmp, *p_emb, *p_si, *p_logit, *p_hbig, *p_W2;
    float *p_psum1, *p_psq1, *p_psum2, *p_psq2, *p_mean1, *p_istd1, *p_mean2, *p_istd2;
    cudaGetSymbolAddress((void**)&p_h400,  g_h400);
    cudaGetSymbolAddress((void**)&p_out,   g_out);
    cudaGetSymbolAddress((void**)&p_tmp,   g_tmp);
    cudaGetSymbolAddress((void**)&p_emb,   g_emb);
    cudaGetSymbolAddress((void**)&p_si,    g_si);
    cudaGetSymbolAddress((void**)&p_logit, g_logit);
    cudaGetSymbolAddress((void**)&p_hbig,  g_hbig);
    cudaGetSymbolAddress((void**)&p_W2,    g_W2);
    cudaGetSymbolAddress((void**)&p_psum1, g_psum1);
    cudaGetSymbolAddress((void**)&p_psq1,  g_psq1);
    cudaGetSymbolAddress((void**)&p_psum2, g_psum2);
    cudaGetSymbolAddress((void**)&p_psq2,  g_psq2);
    cudaGetSymbolAddress((void**)&p_mean1, g_mean1);
    cudaGetSymbolAddress((void**)&p_istd1, g_istd1);
    cudaGetSymbolAddress((void**)&p_mean2, g_mean2);
    cudaGetSymbolAddress((void**)&p_istd2, g_istd2);

    dim3 blk(256);
    auto grid2 = [](int N){ return dim3((unsigned)((N+127)/128), BATCH/128); };

    // base path (TC): out = relu(x@W0+b0)@W1 + b1
    tgemm_tc<<<grid2(400), blk>>>(x,      base_W0, base_b0, p_h400, nullptr, nullptr, 400, 128, EPI_RELU);
    tgemm_tc<<<grid2(256), blk>>>(p_h400, base_W1, base_b1, p_out,  nullptr, nullptr, 256, 400, EPI_NONE);

    // embedding path (TC)
    tgemm_tc<<<grid2(400), blk>>>(embIn,  em_W0,  em_b0,  p_h400, nullptr, nullptr, 400, 128, EPI_RELU);
    tgemm_tc<<<grid2(256), blk>>>(p_h400, gat_W0, gat_b0, p_tmp,  nullptr, nullptr, 256, 400, EPI_RELU);
    tgemm_tc<<<grid2(256), blk>>>(p_tmp,  gat_W1, gat_b1, p_emb,  p_si,    nullptr, 256, 256, EPI_DUAL);

    // select loop (TC, split-bf16 precision ~1e-5)
    for (int i = 0; i < 3; i++) {
        tgemm_tc<<<grid2(64),  blk>>>(p_si, sel_W + (size_t)i*256*64, sel_b + i*64,
                                      p_logit, nullptr, nullptr, 64, 256, EPI_TANH);
        gumbel_sel<<<(BATCH*8+255)/256, blk>>>(u_sel, i);
        tgemm_tc<<<grid2(256), blk>>>(p_logit, cond_W + (size_t)i*64*256, cond_b + i*256,
                                      p_si, nullptr, p_emb, 256, 64, EPI_MULRELU);
    }

    // final select
    gemm_selF<<<BATCH/32, blk>>>(selF_W, selF_b);
    gumbel_fin<<<(BATCH+255)/256, blk>>>(u_fin);

    // bn1 stats over g_out
    colstats<<<dim3(1, NPART), blk>>>(p_out, p_psum1, p_psq1, 256);
    bnfinal<<<1, blk>>>(p_psum1, p_psq1, p_mean1, p_istd1, 256);

    // fold istd1*bn1_g into mod weights (all per-column shifts cancel in bn2)
    scaleW<<<2048, blk>>>(mod_W, bn1_g);

    // mod einsum as ONE plain TC GEMM: hbig[B][2048] = g_out @ W2
    tgemm_tc<<<grid2(2048), blk>>>(p_out, p_W2, nullptr, p_hbig, nullptr, nullptr, 2048, 256, EPI_NONE);

    // bn2 stats over hbig [B][2048]
    colstats<<<dim3(8, NPART), blk>>>(p_hbig, p_psum2, p_psq2, 2048);
    bnfinal<<<8, blk>>>(p_psum2, p_psq2, p_mean2, p_istd2, 2048);

    // fused bn2 + cascade + final select + last layer
    cascade<<<BATCH, blk>>>(bn2_g, bn2_b, last_W, last_b, out);
}

// round 8
// speedup vs baseline: 1.3527x; 1.0224x over previous
#include <cuda_runtime.h>
#include <cuda_bf16.h>
#include <math.h>
#include <stdint.h>
#include <mma.h>

using namespace nvcuda;

#define BATCH 16384

// ---------------- scratch (static device arrays; no allocations) ----------------
__device__ float g_h400 [BATCH*400];
__device__ float g_out  [BATCH*256];
__device__ float g_tmp  [BATCH*256];
__device__ float g_emb  [BATCH*256];
__device__ float g_si   [BATCH*256];
__device__ float g_gsel [3*BATCH*64];
__device__ float g_fsel [BATCH*8];
__device__ float g_hbig [(size_t)BATCH*2048];   // [B][2048], col = m*256+n
__device__ float g_W2   [256*2048];             // [d][m*256+n] scaled mod weights

// deterministic two-stage batchnorm reductions (no atomics)
#define NPART 64
__device__ float g_psum1[NPART*256],  g_psq1[NPART*256];
__device__ float g_psum2[NPART*2048], g_psq2[NPART*2048];
__device__ float g_mean1[256],  g_istd1[256];
__device__ float g_mean2[2048], g_istd2[2048];

enum { EPI_NONE=0, EPI_RELU=1, EPI_TANH=2, EPI_MULRELU=3, EPI_DUAL=4 };

// =======================================================================
//  Split-BF16 TC GEMM (R7, proven): BK=32, vectorized loads, packed
//  uint4 smem stores, staged or direct epilogue. 128x128x32 tile.
// =======================================================================
#define ASTR2 72    // A smem row stride in bf16 (144B): 32 hi | 32 lo | pad
#define BSTR2 264   // B smem row stride in bf16 (528B): 128 hi | 128 lo | pad
#define STG_LD 36

__device__ __forceinline__ uint32_t pack_hi(float v0, float v1, float& r0, float& r1) {
    __nv_bfloat16 h0 = __float2bfloat16(v0);
    __nv_bfloat16 h1 = __float2bfloat16(v1);
    r0 = v0 - __bfloat162float(h0);
    r1 = v1 - __bfloat162float(h1);
    return (uint32_t)__bfloat16_as_ushort(h0) | ((uint32_t)__bfloat16_as_ushort(h1) << 16);
}
__device__ __forceinline__ uint32_t pack_lo(float r0, float r1) {
    __nv_bfloat16 l0 = __float2bfloat16(r0);
    __nv_bfloat16 l1 = __float2bfloat16(r1);
    return (uint32_t)__bfloat16_as_ushort(l0) | ((uint32_t)__bfloat16_as_ushort(l1) << 16);
}

__global__ void __launch_bounds__(256,2) tgemm_tc(
    const float* __restrict__ A, const float* __restrict__ Bw,
    const float* __restrict__ bias, float* __restrict__ C,
    float* __restrict__ C2, const float* __restrict__ aux,
    int N, int K, int epi)
{
    __shared__ __align__(16) char sh[128*ASTR2*2 + 32*BSTR2*2];
    __nv_bfloat16* As = (__nv_bfloat16*)sh;
    __nv_bfloat16* Bs = (__nv_bfloat16*)(sh + 128*ASTR2*2);

    const int tid  = threadIdx.x;
    const int lane = tid & 31, wid = tid >> 5;
    const int warpM = (wid >> 2) * 64, warpN = (wid & 3) * 32;
    const int rowBase = blockIdx.y * 128, colBase = blockIdx.x * 128;

    const int aRow = tid >> 1, aKo = (tid & 1) * 16;
    const int bKr  = tid >> 3, bNo = (tid & 7) * 16;

    wmma::fragment<wmma::accumulator,16,16,16,float> acc[4][2];
    #pragma unroll
    for (int mt=0;mt<4;mt++)
        #pragma unroll
        for (int nt=0;nt<2;nt++)
            wmma::fill_fragment(acc[mt][nt], 0.f);

    for (int kt = 0; kt < K; kt += 32) {
        {
            float va[16];
            const float* ap = A + (size_t)(rowBase + aRow) * K + kt + aKo;
            if (kt + aKo + 15 < K) {
                float4 v0 = *(const float4*)(ap);
                float4 v1 = *(const float4*)(ap + 4);
                float4 v2 = *(const float4*)(ap + 8);
                float4 v3 = *(const float4*)(ap + 12);
                va[0]=v0.x; va[1]=v0.y; va[2]=v0.z; va[3]=v0.w;
                va[4]=v1.x; va[5]=v1.y; va[6]=v1.z; va[7]=v1.w;
                va[8]=v2.x; va[9]=v2.y; va[10]=v2.z; va[11]=v2.w;
                va[12]=v3.x; va[13]=v3.y; va[14]=v3.z; va[15]=v3.w;
            } else {
                #pragma unroll
                for (int e=0;e<16;e++) va[e] = (kt + aKo + e < K) ? ap[e] : 0.f;
            }
            uint32_t ph[8], pl[8];
            float r0, r1;
            #pragma unroll
            for (int e=0;e<8;e++) {
                ph[e] = pack_hi(va[2*e], va[2*e+1], r0, r1);
                pl[e] = pack_lo(r0, r1);
            }
            uint4* dh = (uint4*)((char*)As + aRow*144 + aKo*2);
            dh[0] = make_uint4(ph[0],ph[1],ph[2],ph[3]);
            dh[1] = make_uint4(ph[4],ph[5],ph[6],ph[7]);
            uint4* dl = (uint4*)((char*)As + aRow*144 + 64 + aKo*2);
            dl[0] = make_uint4(pl[0],pl[1],pl[2],pl[3]);
            dl[1] = make_uint4(pl[4],pl[5],pl[6],pl[7]);
        }
        {
            float vb[16];
            int gc = colBase + bNo;
            const float* bp = Bw + (size_t)(kt + bKr) * N + gc;
            if (kt + bKr < K && gc + 15 < N) {
                float4 v0 = *(const float4*)(bp);
                float4 v1 = *(const float4*)(bp + 4);
                float4 v2 = *(const float4*)(bp + 8);
                float4 v3 = *(const float4*)(bp + 12);
                vb[0]=v0.x; vb[1]=v0.y; vb[2]=v0.z; vb[3]=v0.w;
                vb[4]=v1.x; vb[5]=v1.y; vb[6]=v1.z; vb[7]=v1.w;
                vb[8]=v2.x; vb[9]=v2.y; vb[10]=v2.z; vb[11]=v2.w;
                vb[12]=v3.x; vb[13]=v3.y; vb[14]=v3.z; vb[15]=v3.w;
            } else {
                bool krow_ok = (kt + bKr < K);
                #pragma unroll
                for (int e=0;e<16;e++) vb[e] = (krow_ok && gc + e < N) ? bp[e] : 0.f;
            }
            uint32_t ph[8], pl[8];
            float r0, r1;
            #pragma unroll
            for (int e=0;e<8;e++) {
                ph[e] = pack_hi(vb[2*e], vb[2*e+1], r0, r1);
                pl[e] = pack_lo(r0, r1);
            }
            uint4* dh = (uint4*)((char*)Bs + bKr*528 + bNo*2);
            dh[0] = make_uint4(ph[0],ph[1],ph[2],ph[3]);
            dh[1] = make_uint4(ph[4],ph[5],ph[6],ph[7]);
            uint4* dl = (uint4*)((char*)Bs + bKr*528 + 256 + bNo*2);
            dl[0] = make_uint4(pl[0],pl[1],pl[2],pl[3]);
            dl[1] = make_uint4(pl[4],pl[5],pl[6],pl[7]);
        }
        __syncthreads();

        #pragma unroll
        for (int ks=0; ks<32; ks+=16) {
            wmma::fragment<wmma::matrix_b,16,16,16,__nv_bfloat16,wmma::row_major> bh[2], bl[2];
            #pragma unroll
            for (int nt=0;nt<2;nt++) {
                wmma::load_matrix_sync(bh[nt], &Bs[ks*BSTR2 + warpN + nt*16],       BSTR2);
                wmma::load_matrix_sync(bl[nt], &Bs[ks*BSTR2 + 128 + warpN + nt*16], BSTR2);
            }
            #pragma unroll
            for (int mt=0;mt<4;mt++) {
                wmma::fragment<wmma::matrix_a,16,16,16,__nv_bfloat16,wmma::row_major> ah, al;
                wmma::load_matrix_sync(ah, &As[(warpM + mt*16)*ASTR2 + ks],      ASTR2);
                wmma::load_matrix_sync(al, &As[(warpM + mt*16)*ASTR2 + 32 + ks], ASTR2);
                #pragma unroll
                for (int nt=0;nt<2;nt++) {
                    wmma::mma_sync(acc[mt][nt], ah, bh[nt], acc[mt][nt]);
                    wmma::mma_sync(acc[mt][nt], ah, bl[nt], acc[mt][nt]);
                    wmma::mma_sync(acc[mt][nt], al, bh[nt], acc[mt][nt]);
                }
            }
        }
        __syncthreads();
    }

    if (bias == nullptr && epi == EPI_NONE) {
        #pragma unroll
        for (int mt=0; mt<4; mt++) {
            float* dst = C + (size_t)(rowBase + warpM + mt*16) * N + colBase + warpN;
            wmma::store_matrix_sync(dst,      acc[mt][0], N, wmma::mem_row_major);
            wmma::store_matrix_sync(dst + 16, acc[mt][1], N, wmma::mem_row_major);
        }
        return;
    }

    float* stg = (float*)sh + wid * (16*STG_LD);
    const int r  = lane >> 1;
    const int cb = (lane & 1) * 16;
    #pragma unroll
    for (int mt=0; mt<4; mt++) {
        wmma::store_matrix_sync(stg,      acc[mt][0], STG_LD, wmma::mem_row_major);
        wmma::store_matrix_sync(stg + 16, acc[mt][1], STG_LD, wmma::mem_row_major);
        __syncwarp();
        int row  = rowBase + warpM + mt*16 + r;
        int col0 = colBase + warpN + cb;
        if (col0 < N) {
            size_t base = (size_t)row * N + col0;
            #pragma unroll
            for (int e=0;e<16;e++) {
                float v = stg[r*STG_LD + cb + e] + bias[col0 + e];
                if      (epi == EPI_NONE)    C[base + e] = v;
                else if (epi == EPI_RELU)    C[base + e] = fmaxf(v, 0.f);
                else if (epi == EPI_TANH)    C[base + e] = tanhf(v);
                else if (epi == EPI_MULRELU) C[base + e] = fmaxf(v * aux[base + e], 0.f);
                else { C[base + e] = v; C2[base + e] = fmaxf(v, 0.f); }
            }
        }
        __syncwarp();
    }
}

// ---------------- gumbel noise ----------------
__device__ __forceinline__ float gnoise(float u) {
    u = fminf(fmaxf(u, 1e-10f), 1.0f - 1e-7f);
    return -logf(-logf(u));
}

// =======================================================================
//  Fused select step:
//    logit = tanh(si @ selW + selb)        (TC, M128xN64, K=256)
//    gsel  = gumbel_softmax(logit, u)      (in-smem)
//    si    = relu((logit @ condW + condb) * emb)   (TC, K=64, in-place)
//  Dynamic smem regions (sequenced overlays):
//    [0,18432)      A1 tile (128 x 144B)
//    [18432,27136)  B1 tile (32 x 272B)
//    [0,34816)      STG fp32 logits (128 x 68 f32)     after phase-1 loop
//    [34816,69632)  LGT bf16 hi/lo logits (128 x 272B) persists phase 2
//    [0,33792)      B2 tile (64 x 528B)                per N-half
//    [0,18432)      stg2 per-warp epilogue staging     after half's mma
// =======================================================================
__global__ void __launch_bounds__(256) selstep(
    const float* __restrict__ selW, const float* __restrict__ selb,
    const float* __restrict__ condW, const float* __restrict__ condb,
    const float* __restrict__ u, int it)
{
    extern __shared__ __align__(16) char dsm[];
    __nv_bfloat16* A1  = (__nv_bfloat16*)dsm;
    __nv_bfloat16* B1  = (__nv_bfloat16*)(dsm + 18432);
    float*         STG = (float*)dsm;
    __nv_bfloat16* LGT = (__nv_bfloat16*)(dsm + 34816);
    __nv_bfloat16* B2  = (__nv_bfloat16*)dsm;

    const int tid  = threadIdx.x;
    const int lane = tid & 31, wid = tid >> 5;
    const int rowBase = blockIdx.x * 128;

    // ---------------- phase 1: logit GEMM (M128 x N64, K=256) ----------------
    const int warpM1 = (wid >> 1) * 32, warpN1 = (wid & 1) * 32;
    const int aRow = tid >> 1, aKo = (tid & 1) * 16;
    const int bKr  = tid >> 3, bNo = (tid & 7) * 8;

    wmma::fragment<wmma::accumulator,16,16,16,float> acc1[2][2];
    #pragma unroll
    for (int mt=0;mt<2;mt++)
        #pragma unroll
        for (int nt=0;nt<2;nt++)
            wmma::fill_fragment(acc1[mt][nt], 0.f);

    for (int kt = 0; kt < 256; kt += 32) {
        {   // A tile from g_si
            const float* ap = g_si + (size_t)(rowBase + aRow) * 256 + kt + aKo;
            float4 v0 = *(const float4*)(ap);
            float4 v1 = *(const float4*)(ap + 4);
            float4 v2 = *(const float4*)(ap + 8);
            float4 v3 = *(const float4*)(ap + 12);
            float va[16] = {v0.x,v0.y,v0.z,v0.w, v1.x,v1.y,v1.z,v1.w,
                            v2.x,v2.y,v2.z,v2.w, v3.x,v3.y,v3.z,v3.w};
            uint32_t ph[8], pl[8];
            float r0, r1;
            #pragma unroll
            for (int e=0;e<8;e++) {
                ph[e] = pack_hi(va[2*e], va[2*e+1], r0, r1);
                pl[e] = pack_lo(r0, r1);
            }
            uint4* dh = (uint4*)((char*)A1 + aRow*144 + aKo*2);
            dh[0] = make_uint4(ph[0],ph[1],ph[2],ph[3]);
            dh[1] = make_uint4(ph[4],ph[5],ph[6],ph[7]);
            uint4* dl = (uint4*)((char*)A1 + aRow*144 + 64 + aKo*2);
            dl[0] = make_uint4(pl[0],pl[1],pl[2],pl[3]);
            dl[1] = make_uint4(pl[4],pl[5],pl[6],pl[7]);
        }
        {   // B tile from selW [256][64], rows kt+bKr, cols bNo..+8
            const float* bp = selW + (size_t)(kt + bKr) * 64 + bNo;
            float4 w0 = *(const float4*)(bp);
            float4 w1 = *(const float4*)(bp + 4);
            float vb[8] = {w0.x,w0.y,w0.z,w0.w, w1.x,w1.y,w1.z,w1.w};
            uint32_t ph[4], pl[4];
            float r0, r1;
            #pragma unroll
            for (int e=0;e<4;e++) {
                ph[e] = pack_hi(vb[2*e], vb[2*e+1], r0, r1);
                pl[e] = pack_lo(r0, r1);
            }
            *(uint4*)((char*)B1 + bKr*272 + bNo*2)       = make_uint4(ph[0],ph[1],ph[2],ph[3]);
            *(uint4*)((char*)B1 + bKr*272 + 128 + bNo*2) = make_uint4(pl[0],pl[1],pl[2],pl[3]);
        }
        __syncthreads();

        #pragma unroll
        for (int ks=0; ks<32; ks+=16) {
            wmma::fragment<wmma::matrix_b,16,16,16,__nv_bfloat16,wmma::row_major> bh[2], bl[2];
            #pragma unroll
            for (int nt=0;nt<2;nt++) {
                wmma::load_matrix_sync(bh[nt], &B1[ks*136 + warpN1 + nt*16],      136);
                wmma::load_matrix_sync(bl[nt], &B1[ks*136 + 64 + warpN1 + nt*16], 136);
            }
            #pragma unroll
            for (int mt=0;mt<2;mt++) {
                wmma::fragment<wmma::matrix_a,16,16,16,__nv_bfloat16,wmma::row_major> ah, al;
                wmma::load_matrix_sync(ah, &A1[(warpM1 + mt*16)*72 + ks],      72);
                wmma::load_matrix_sync(al, &A1[(warpM1 + mt*16)*72 + 32 + ks], 72);
                #pragma unroll
                for (int nt=0;nt<2;nt++) {
                    wmma::mma_sync(acc1[mt][nt], ah, bh[nt], acc1[mt][nt]);
                    wmma::mma_sync(acc1[mt][nt], ah, bl[nt], acc1[mt][nt]);
                    wmma::mma_sync(acc1[mt][nt], al, bh[nt], acc1[mt][nt]);
                }
            }
        }
        __syncthreads();
    }

    // stage logits to STG (overlays A1/B1; tiles dead after trailing sync)
    #pragma unroll
    for (int mt=0;mt<2;mt++)
        #pragma unroll
        for (int nt=0;nt<2;nt++)
            wmma::store_matrix_sync(&STG[(warpM1 + mt*16)*68 + warpN1 + nt*16],
                                    acc1[mt][nt], 68, wmma::mem_row_major);
    __syncthreads();

    // tanh + bias, write back STG, split to LGT bf16 hi/lo
    {
        int row = tid >> 1, c0 = (tid & 1) * 32;
        #pragma unroll
        for (int e=0;e<32;e++) {
            int col = c0 + e;
            float v = STG[row*68 + col];
            v = tanhf(v + selb[col]);
            STG[row*68 + col] = v;
            __nv_bfloat16 h = __float2bfloat16(v);
            __nv_bfloat16 l = __float2bfloat16(v - __bfloat162float(h));
            LGT[row*136 + col]      = h;
            LGT[row*136 + 64 + col] = l;
        }
    }
    __syncthreads();

    // gumbel softmax per (row, m-group of 8): 1024 groups, 4 per thread
    #pragma unroll
    for (int j=0;j<4;j++) {
        int gid = tid*4 + j;
        int row = gid >> 3, mg = gid & 7;
        int b = rowBase + row;
        const float* up = u + (size_t)b*192 + it*64 + mg*8;
        float z[8]; float mx = -3.4e38f;
        #pragma unroll
        for (int k=0;k<8;k++){ z[k] = STG[row*68 + mg*8 + k] + gnoise(up[k]); mx = fmaxf(mx, z[k]); }
        float s = 0.f;
        #pragma unroll
        for (int k=0;k<8;k++){ z[k] = expf(z[k]-mx); s += z[k]; }
        float inv = 1.f/s;
        float* op = g_gsel + (size_t)it*BATCH*64 + (size_t)b*64 + mg*8;
        #pragma unroll
        for (int k=0;k<8;k++) op[k] = z[k]*inv;
    }
    __syncthreads();   // STG dead; B2 region free

    // ---------------- phase 2: si' = relu((logit @ condW + b) * emb) ----------------
    const int warpM2 = (wid >> 2) * 64, warpN2 = (wid & 3) * 32;
    const int bk2 = tid >> 2, bn2 = (tid & 3) * 32;
    const int r  = lane >> 1, cb = (lane & 1) * 16;

    for (int nh = 0; nh < 2; nh++) {
        {   // B2 tile: condW [64][256], cols nh*128 + bn2 .. +32
            const float* bp = condW + (size_t)bk2*256 + nh*128 + bn2;
            float vb[32];
            #pragma unroll
            for (int q=0;q<8;q++) {
                float4 w = *(const float4*)(bp + q*4);
                vb[q*4+0]=w.x; vb[q*4+1]=w.y; vb[q*4+2]=w.z; vb[q*4+3]=w.w;
            }
            uint32_t ph[16], pl[16];
            float r0, r1;
            #pragma unroll
            for (int e=0;e<16;e++) {
                ph[e] = pack_hi(vb[2*e], vb[2*e+1], r0, r1);
                pl[e] = pack_lo(r0, r1);
            }
            uint4* dh = (uint4*)((char*)B2 + bk2*528 + bn2*2);
            uint4* dl = (uint4*)((char*)B2 + bk2*528 + 256 + bn2*2);
            #pragma unroll
            for (int q=0;q<4;q++) {
                dh[q] = make_uint4(ph[q*4],ph[q*4+1],ph[q*4+2],ph[q*4+3]);
                dl[q] = make_uint4(pl[q*4],pl[q*4+1],pl[q*4+2],pl[q*4+3]);
            }
        }
        __syncthreads();

        wmma::fragment<wmma::accumulator,16,16,16,float> acc2[4][2];
        #pragma unroll
        for (int mt=0;mt<4;mt++)
            #pragma unroll
            for (int nt=0;nt<2;nt++)
                wmma::fill_fragment(acc2[mt][nt], 0.f);

        #pragma unroll
        for (int ks=0; ks<64; ks+=16) {
            wmma::fragment<wmma::matrix_b,16,16,16,__nv_bfloat16,wmma::row_major> bh[2], bl[2];
            #pragma unroll
            for (int nt=0;nt<2;nt++) {
                wmma::load_matrix_sync(bh[nt], &B2[ks*264 + warpN2 + nt*16],       264);
                wmma::load_matrix_sync(bl[nt], &B2[ks*264 + 128 + warpN2 + nt*16], 264);
            }
            #pragma unroll
            for (int mt=0;mt<4;mt++) {
                wmma::fragment<wmma::matrix_a,16,16,16,__nv_bfloat16,wmma::row_major> ah, al;
                wmma::load_matrix_sync(ah, &LGT[(warpM2 + mt*16)*136 + ks],      136);
                wmma::load_matrix_sync(al, &LGT[(warpM2 + mt*16)*136 + 64 + ks], 136);
                #pragma unroll
                for (int nt=0;nt<2;nt++) {
                    wmma::mma_sync(acc2[mt][nt], ah, bh[nt], acc2[mt][nt]);
                    wmma::mma_sync(acc2[mt][nt], ah, bl[nt], acc2[mt][nt]);
                    wmma::mma_sync(acc2[mt][nt], al, bh[nt], acc2[mt][nt]);
                }
            }
        }
        __syncthreads();   // B2 dead -> stg2 may overlay

        float* stg2 = (float*)dsm + wid * (16*STG_LD);
        #pragma unroll
        for (int mt=0; mt<4; mt++) {
            wmma::store_matrix_sync(stg2,      acc2[mt][0], STG_LD, wmma::mem_row_major);
            wmma::store_matrix_sync(stg2 + 16, acc2[mt][1], STG_LD, wmma::mem_row_major);
            __syncwarp();
            int row  = rowBase + warpM2 + mt*16 + r;
            int col0 = nh*128 + warpN2 + cb;
            size_t base = (size_t)row * 256 + col0;
            #pragma unroll
            for (int e=0;e<16;e++) {
                float v = stg2[r*STG_LD + cb + e] + condb[col0 + e];
                v *= g_emb[base + e];
                g_si[base + e] = fmaxf(v, 0.f);
            }
            __syncwarp();
        }
        __syncthreads();   // stg2 dead before next half's B2 load
    }
}

// ---------------- scaled mod weights ----------------
__global__ void scaleW(const float* __restrict__ modW, const float* __restrict__ g1)
{
    int idx = blockIdx.x*256 + threadIdx.x;
    int d = idx >> 11;
    int c = idx & 2047;
    int m = c >> 8;
    int n = c & 255;
    g_W2[idx] = g_istd1[d] * g1[m*256 + d] * modW[((size_t)(m*256 + d))*256 + n];
}

// ---------------- batchnorm stats (deterministic 2-stage) ----------------
__global__ void colstats(const float* __restrict__ X,
                         float* __restrict__ psum, float* __restrict__ psq,
                         int ncols)
{
    int c = blockIdx.x*256 + threadIdx.x;
    int rpb = BATCH / NPART;
    int r0  = blockIdx.y * rpb;
    float s = 0.f, q = 0.f;
    for (int r = r0; r < r0 + rpb; r++) {
        float v = X[(size_t)r*ncols + c];
        s += v; q += v*v;
    }
    psum[(size_t)blockIdx.y*ncols + c] = s;
    psq [(size_t)blockIdx.y*ncols + c] = q;
}

__global__ void bnfinal(const float* __restrict__ psum, const float* __restrict__ psq,
                        float* __restrict__ mean, float* __restrict__ istd, int n)
{
    int i = blockIdx.x*blockDim.x + threadIdx.x;
    if (i >= n) return;
    float s = 0.f, q = 0.f;
    for (int p = 0; p < NPART; p++) { s += psum[(size_t)p*n + i]; q += psq[(size_t)p*n + i]; }
    float mu  = s * (1.f/BATCH);
    float var = q * (1.f/BATCH) - mu*mu;
    mean[i] = mu;
    istd[i] = rsqrtf(var + 1e-5f);
}

// ---------------- final select logits + fused gumbel ----------------
__global__ void __launch_bounds__(256) gemm_selF(
    const float* __restrict__ W, const float* __restrict__ bias,
    const float* __restrict__ u)
{
    __shared__ float Ws[2048];
    int tid = threadIdx.x;
    for (int idx = tid; idx < 2048; idx += 256) Ws[idx] = W[idx];
    __syncthreads();
    int b = blockIdx.x*32 + (tid >> 3);
    int n = tid & 7;
    const float* ap = g_si + (size_t)b*256;
    float acc = bias[n];
    #pragma unroll 8
    for (int k=0;k<256;k++) acc += ap[k]*Ws[k*8+n];
    // fused gumbel softmax across the 8 lanes sharing b
    float z = acc + gnoise(u[b*8 + n]);
    float mx = z;
    #pragma unroll
    for (int o=1;o<8;o<<=1) mx = fmaxf(mx, __shfl_xor_sync(0xffffffff, mx, o));
    float e = expf(z - mx);
    float s = e;
    #pragma unroll
    for (int o=1;o<8;o<<=1) s += __shfl_xor_sync(0xffffffff, s, o);
    g_fsel[b*8 + n] = e / s;
}

// ---------------- fused bn2 + select cascade + final select + last GEMM ----------------
__global__ void __launch_bounds__(256) cascade(
    const float* __restrict__ g2, const float* __restrict__ b2,
    const float* __restrict__ lastW, const float* __restrict__ lastb,
    float* __restrict__ out)
{
    int b = blockIdx.x;
    int tid = threadIdx.x;
    __shared__ float Ssh[64];
    __shared__ float fs[8];
    __shared__ float ov[256];

    float p[8];
    #pragma unroll
    for (int m=0;m<8;m++) {
        int c = m*256 + tid;
        float v = g_hbig[(size_t)b*2048 + c];
        p[m] = (v - g_mean2[c]) * g_istd2[c] * g2[c] + b2[c];
    }

    for (int l=0;l<3;l++) {
        if (tid < 64) Ssh[tid] = g_gsel[(size_t)(2-l)*BATCH*64 + (size_t)b*64 + tid];
        __syncthreads();
        float np[8];
        #pragma unroll
        for (int m=0;m<8;m++) {
            float a = 0.f;
            #pragma unroll
            for (int k=0;k<8;k++) a += Ssh[m*8+k]*p[k];
            np[m] = fmaxf(a, 0.f);
        }
        #pragma unroll
        for (int m=0;m<8;m++) p[m] = np[m];
        __syncthreads();
    }

    if (tid < 8) fs[tid] = g_fsel[b*8+tid];
    __syncthreads();
    float o = 0.f;
    #pragma unroll
    for (int m=0;m<8;m++) o += fs[m]*p[m];
    ov[tid] = o;
    __syncthreads();

    if (tid < 18) {
        float acc = lastb[tid];
        for (int k=0;k<256;k++) acc += ov[k]*lastW[k*18+tid];
        out[(size_t)b*18 + tid] = acc;
    }
}

// ---------------- launch ----------------
extern "C" void kernel_launch(void* const* d_in, const int* in_sizes, int n_in,
                              void* d_out, int out_size)
{
    const float* x       = (const float*)d_in[0];
    const float* embIn   = (const float*)d_in[1];
    const float* u_sel   = (const float*)d_in[2];
    const float* u_fin   = (const float*)d_in[3];
    const float* base_W0 = (const float*)d_in[4];
    const float* base_b0 = (const float*)d_in[5];
    const float* base_W1 = (const float*)d_in[6];
    const float* base_b1 = (const float*)d_in[7];
    const float* em_W0   = (const float*)d_in[8];
    const float* em_b0   = (const float*)d_in[9];
    const float* gat_W0  = (const float*)d_in[10];
    const float* gat_b0  = (const float*)d_in[11];
    const float* gat_W1  = (const float*)d_in[12];
    const float* gat_b1  = (const float*)d_in[13];
    const float* sel_W   = (const float*)d_in[14];
    const float* sel_b   = (const float*)d_in[15];
    const float* selF_W  = (const float*)d_in[16];
    const float* selF_b  = (const float*)d_in[17];
    const float* cond_W  = (const float*)d_in[18];
    const float* cond_b  = (const float*)d_in[19];
    const float* mod_W   = (const float*)d_in[20];
    const float* mod_b   = (const float*)d_in[21];   // cancelled by bn2 (unused)
    const float* last_W  = (const float*)d_in[22];
    const float* last_b  = (const float*)d_in[23];
    const float* bn1_g   = (const float*)d_in[24];
    const float* bn1_b   = (const float*)d_in[25];   // cancelled by bn2 (unused)
    const float* bn2_g   = (const float*)d_in[26];
    const float* bn2_b   = (const float*)d_in[27];
    float* out = (float*)d_out;
    (void)mod_b; (void)bn1_b;

    float *p_h400, *p_out, *p_tmp, *p_emb, *p_si, *p_hbig, *p_W2;
    float *p_psum1, *p_psq1, *p_psum2, *p_psq2, *p_mean1, *p_istd1, *p_mean2, *p_istd2;
    cudaGetSymbolAddress((void**)&p_h400,  g_h400);
    cudaGetSymbolAddress((void**)&p_out,   g_out);
    cudaGetSymbolAddress((void**)&p_tmp,   g_tmp);
    cudaGetSymbolAddress((void**)&p_emb,   g_emb);
    cudaGetSymbolAddress((void**)&p_si,    g_si);
    cudaGetSymbolAddress((void**)&p_hbig,  g_hbig);
    cudaGetSymbolAddress((void**)&p_W2,    g_W2);
    cudaGetSymbolAddress((void**)&p_psum1, g_psum1);
    cudaGetSymbolAddress((void**)&p_psq1,  g_psq1);
    cudaGetSymbolAddress((void**)&p_psum2, g_psum2);
    cudaGetSymbolAddress((void**)&p_psq2,  g_psq2);
    cudaGetSymbolAddress((void**)&p_mean1, g_mean1);
    cudaGetSymbolAddress((void**)&p_istd1, g_istd1);
    cudaGetSymbolAddress((void**)&p_mean2, g_mean2);
    cudaGetSymbolAddress((void**)&p_istd2, g_istd2);

    // allow 68KB dynamic smem for selstep (idempotent host-side call)
    cudaFuncSetAttribute(selstep, cudaFuncAttributeMaxDynamicSharedMemorySize, 69632);

    dim3 blk(256);
    auto grid2 = [](int N){ return dim3((unsigned)((N+127)/128), BATCH/128); };

    // base path (TC): out = relu(x@W0+b0)@W1 + b1
    tgemm_tc<<<grid2(400), blk>>>(x,      base_W0, base_b0, p_h400, nullptr, nullptr, 400, 128, EPI_RELU);
    tgemm_tc<<<grid2(256), blk>>>(p_h400, base_W1, base_b1, p_out,  nullptr, nullptr, 256, 400, EPI_NONE);

    // embedding path (TC)
    tgemm_tc<<<grid2(400), blk>>>(embIn,  em_W0,  em_b0,  p_h400, nullptr, nullptr, 400, 128, EPI_RELU);
    tgemm_tc<<<grid2(256), blk>>>(p_h400, gat_W0, gat_b0, p_tmp,  nullptr, nullptr, 256, 400, EPI_RELU);
    tgemm_tc<<<grid2(256), blk>>>(p_tmp,  gat_W1, gat_b1, p_emb,  p_si,    nullptr, 256, 256, EPI_DUAL);

    // fused select loop: 3 launches
    for (int i = 0; i < 3; i++) {
        selstep<<<BATCH/128, blk, 69632>>>(sel_W + (size_t)i*256*64, sel_b + i*64,
                                           cond_W + (size_t)i*64*256, cond_b + i*256,
                                           u_sel, i);
    }

    // final select (gumbel fused)
    gemm_selF<<<BATCH/32, blk>>>(selF_W, selF_b, u_fin);

    // bn1 stats over g_out
    colstats<<<dim3(1, NPART), blk>>>(p_out, p_psum1, p_psq1, 256);
    bnfinal<<<1, blk>>>(p_psum1, p_psq1, p_mean1, p_istd1, 256);

    // fold istd1*bn1_g into mod weights (per-column shifts cancel in bn2)
    scaleW<<<2048, blk>>>(mod_W, bn1_g);

    // mod einsum as ONE plain TC GEMM: hbig[B][2048] = g_out @ W2
    tgemm_tc<<<grid2(2048), blk>>>(p_out, p_W2, nullptr, p_hbig, nullptr, nullptr, 2048, 256, EPI_NONE);

    // bn2 stats over hbig [B][2048]
    colstats<<<dim3(8, NPART), blk>>>(p_hbig, p_psum2, p_psq2, 2048);
    bnfinal<<<8, blk>>>(p_psum2, p_psq2, p_mean2, p_istd2, 2048);

    // fused bn2 + cascade + final select + last layer
    cascade<<<BATCH, blk>>>(bn2_g, bn2_b, last_W, last_b, out);
}